// round 12
// baseline (speedup 1.0000x reference)
#include <cuda_runtime.h>
#include <cuda_fp16.h>
#include <math.h>
#include <stdint.h>

#define BB 2
#define LL 1024
#define DD 1024
#define EE 2048
#define NST 16
#define DTR 64
#define NLAYER 4
#define ML (BB*LL)          // 2048
#define XDBW (DTR + 2*NST)  // 96
#define SPLITK 8

#define SZ_IPW (NLAYER*2*EE*DD)
#define SZ_XPW (NLAYER*XDBW*EE)
#define SZ_DTW (NLAYER*EE*DTR)
#define SZ_OPW (NLAYER*DD*EE)

// ---------------- scratch (device globals; no allocation) ----------------
__device__ __align__(16) float g_resid[ML*DD];
__device__ __align__(16) float g_xz[ML*2*EE];
__device__ __align__(16) float g_u[ML*EE];
__device__ __align__(16) float g_xdb[ML*XDBW];
__device__ __align__(16) float g_xdb_part[SPLITK*ML*XDBW];
__device__ __align__(16) float g_dt[ML*EE];
__device__ __align__(16) float g_h[ML*DD];

__device__ __align__(16) __half wb_ipw_hi[SZ_IPW], wb_ipw_lo[SZ_IPW];
__device__ __align__(16) __half wb_xpw_hi[SZ_XPW], wb_xpw_lo[SZ_XPW];
__device__ __align__(16) __half wb_dtw_hi[SZ_DTW], wb_dtw_lo[SZ_DTW];
__device__ __align__(16) __half wb_opw_hi[SZ_OPW], wb_opw_lo[SZ_OPW];

__device__ __align__(16) __half a_hn16[ML*DD];
__device__ __align__(16) __half a_u16[ML*EE];
__device__ __align__(16) __half a_dt16[ML*DTR];
__device__ __align__(16) __half a_y16[ML*EE];

// ---------------- helpers ----------------
__device__ __forceinline__ uint32_t smem_to_u32(const void* p) {
    uint32_t a;
    asm("{ .reg .u64 t; cvta.to.shared.u64 t, %1; cvt.u32.u64 %0, t; }" : "=r"(a) : "l"(p));
    return a;
}
__device__ __forceinline__ void cp16(uint32_t s, const void* g) {
    asm volatile("cp.async.cg.shared.global [%0], [%1], 16;" :: "r"(s), "l"(g) : "memory");
}
__device__ __forceinline__ void cp16z(uint32_t s, const void* g, int srcsize) {
    asm volatile("cp.async.cg.shared.global [%0], [%1], 16, %2;"
                 :: "r"(s), "l"(g), "r"(srcsize) : "memory");
}
__device__ __forceinline__ void cp_commit() {
    asm volatile("cp.async.commit_group;" ::: "memory");
}
template <int N>
__device__ __forceinline__ void cp_wait() {
    asm volatile("cp.async.wait_group %0;" :: "n"(N) : "memory");
}
__device__ __forceinline__ void ldm_x4(uint32_t* r, uint32_t addr) {
    asm volatile("ldmatrix.sync.aligned.m8n8.x4.shared.b16 {%0,%1,%2,%3}, [%4];"
                 : "=r"(r[0]), "=r"(r[1]), "=r"(r[2]), "=r"(r[3]) : "r"(addr));
}
__device__ __forceinline__ void mma_f16(float* d, const uint32_t* a, uint32_t b0, uint32_t b1) {
    asm volatile(
        "mma.sync.aligned.m16n8k16.row.col.f32.f16.f16.f32 "
        "{%0,%1,%2,%3}, {%4,%5,%6,%7}, {%8,%9}, {%0,%1,%2,%3};"
        : "+f"(d[0]), "+f"(d[1]), "+f"(d[2]), "+f"(d[3])
        : "r"(a[0]), "r"(a[1]), "r"(a[2]), "r"(a[3]), "r"(b0), "r"(b1));
}
// fp16-accumulator variant (lo product only; its magnitude is ~0.4% of the result)
__device__ __forceinline__ void mma_f16acc(uint32_t* d, const uint32_t* a, uint32_t b0, uint32_t b1) {
    asm volatile(
        "mma.sync.aligned.m16n8k16.row.col.f16.f16.f16.f16 "
        "{%0,%1}, {%2,%3,%4,%5}, {%6,%7}, {%0,%1};"
        : "+r"(d[0]), "+r"(d[1])
        : "r"(a[0]), "r"(a[1]), "r"(a[2]), "r"(a[3]), "r"(b0), "r"(b1));
}
__device__ __forceinline__ void hsplit2(float x, __half& h, __half& l) {
    h = __float2half(x);
    l = __float2half(x - __half2float(h));
}

// ---------------- HMMA GEMM: C = A16*(Bhi+Blo)^T; hi->f32 accum, lo->f16 accum ----------------
#define KC 64
#define NSTG 3
#define ROWB 144
#define TILE_B (128*ROWB)           // 18432
#define STAGE_B (3*TILE_B)          // 55296
#define GSMEM (NSTG*STAGE_B)        // 165888

template <int MODE>
__global__ void __launch_bounds__(256, 1)
hmma_gemm(const __half* __restrict__ A16,
          const __half* __restrict__ Bhi, const __half* __restrict__ Blo,
          float* __restrict__ C, int N, int Kloop, int lda, int ldb,
          size_t czstride, const float* __restrict__ bias)
{
    extern __shared__ char smem[];
    const uint32_t sb = smem_to_u32(smem);
    const int tid  = threadIdx.x;
    const int wid  = tid >> 5;
    const int lane = tid & 31;
    const int wm = wid >> 2;
    const int wn = wid & 3;
    const int row0 = blockIdx.y * 128;
    const int col0 = blockIdx.x * 128;
    const int kbase = blockIdx.z * Kloop;

    const __half* Bsrc[2] = {Bhi, Blo};

    const int nc = Kloop / KC;

    auto stage_of = [&](int c) { int m = c % NSTG; return (uint32_t)m * STAGE_B; };

    auto load_chunk = [&](int c) {
        if (c < nc) {
            const uint32_t base = sb + stage_of(c);
            const int k0 = kbase + c * KC;
            #pragma unroll
            for (int it = 0; it < 12; it++) {
                int s = tid + it * 256;
                int tile = s >> 10;          // 0..2
                int r = (s >> 3) & 127;
                int seg = s & 7;
                uint32_t off = base + (uint32_t)tile * TILE_B + (uint32_t)(r * ROWB + seg * 16);
                if (tile == 0) {
                    const __half* g = A16 + ((size_t)(row0 + r) * lda + k0 + seg * 8);
                    cp16(off, g);
                } else {
                    const __half* g = Bsrc[tile - 1] + ((size_t)(col0 + r) * ldb + k0 + seg * 8);
                    cp16z(off, g, (col0 + r < N) ? 16 : 0);
                }
            }
        }
        cp_commit();
    };

    float acc[4][4][4];
    uint32_t acc16[4][4][2];
    #pragma unroll
    for (int i = 0; i < 4; i++)
        #pragma unroll
        for (int j = 0; j < 4; j++) {
            #pragma unroll
            for (int k = 0; k < 4; k++) acc[i][j][k] = 0.f;
            acc16[i][j][0] = 0u; acc16[i][j][1] = 0u;
        }

    load_chunk(0);
    load_chunk(1);

    for (int c = 0; c < nc; c++) {
        cp_wait<NSTG - 2>();
        __syncthreads();

        const uint32_t base = sb + stage_of(c);

        #pragma unroll
        for (int s = 0; s < 4; s++) {
            uint32_t af[4][4];      // [mtile][reg]
            uint32_t bf[2][2][4];   // [hilo][n16 block][reg]

            #pragma unroll
            for (int mi = 0; mi < 4; mi++) {
                uint32_t addr = base
                    + (uint32_t)((wm * 64 + mi * 16 + (lane & 15)) * ROWB
                                 + s * 32 + (lane >> 4) * 16);
                ldm_x4(af[mi], addr);
            }
            #pragma unroll
            for (int t = 0; t < 2; t++) {
                #pragma unroll
                for (int nb = 0; nb < 2; nb++) {
                    uint32_t addr = base + (uint32_t)(1 + t) * TILE_B
                        + (uint32_t)((wn * 32 + nb * 16 + ((lane >> 4) & 1) * 8 + (lane & 7)) * ROWB
                                     + ((lane >> 3) & 1) * 16 + s * 32);
                    ldm_x4(bf[t][nb], addr);
                }
            }

            if (s == 0) load_chunk(c + 2);

            #pragma unroll
            for (int mi = 0; mi < 4; mi++) {
                #pragma unroll
                for (int n = 0; n < 4; n++) {
                    int nb = n >> 1, o = (n & 1) * 2;
                    mma_f16(acc[mi][n], af[mi], bf[0][nb][o], bf[0][nb][o + 1]);        // hi -> f32
                    mma_f16acc(acc16[mi][n], af[mi], bf[1][nb][o], bf[1][nb][o + 1]);   // lo -> f16
                }
            }
        }
    }

    float* Cz = C + (size_t)blockIdx.z * czstride;
    #pragma unroll
    for (int mi = 0; mi < 4; mi++) {
        #pragma unroll
        for (int n = 0; n < 4; n++) {
            int colb = col0 + wn * 32 + n * 8 + (lane & 3) * 2;
            #pragma unroll
            for (int half = 0; half < 2; half++) {
                int row = row0 + wm * 64 + mi * 16 + (lane >> 2) + half * 8;
                if (colb < N) {
                    __half2 lo2 = *(__half2*)&acc16[mi][n][half];
                    float v0 = acc[mi][n][half * 2 + 0] + __half2float(__low2half(lo2));
                    float v1 = acc[mi][n][half * 2 + 1] + __half2float(__high2half(lo2));
                    if (MODE == 1) {
                        v0 += bias[colb];
                        v1 += bias[colb + 1];
                        v0 = (v0 > 20.f) ? v0 : log1pf(__expf(v0));
                        v1 = (v1 > 20.f) ? v1 : log1pf(__expf(v1));
                    }
                    *(float2*)&Cz[(size_t)row * N + colb] = make_float2(v0, v1);
                }
            }
        }
    }
}

// ---------------- merged weight split (fp16 hi/lo) ----------------
#define N4_IPW (SZ_IPW/4)
#define N4_OPW (SZ_OPW/4)
#define N4_XPW (SZ_XPW/4)
#define N4_DTW (SZ_DTW/4)
#define N4_ALL (N4_IPW+N4_OPW+N4_XPW+N4_DTW)

__global__ void wsplit_all_kernel(const float4* __restrict__ ipw,
                                  const float4* __restrict__ opw,
                                  const float4* __restrict__ xpw,
                                  const float4* __restrict__ dtw,
                                  __half2* __restrict__ ipw_hi, __half2* __restrict__ ipw_lo,
                                  __half2* __restrict__ opw_hi, __half2* __restrict__ opw_lo,
                                  __half2* __restrict__ xpw_hi, __half2* __restrict__ xpw_lo,
                                  __half2* __restrict__ dtw_hi, __half2* __restrict__ dtw_lo)
{
    int i = blockIdx.x * 256 + threadIdx.x;
    if (i >= N4_ALL) return;
    const float4* src;
    __half2 *hi, *lo;
    int j = i;
    if (j < N4_IPW)                 { src = ipw; hi = ipw_hi; lo = ipw_lo; }
    else if ((j -= N4_IPW) < N4_OPW){ src = opw; hi = opw_hi; lo = opw_lo; }
    else if ((j -= N4_OPW) < N4_XPW){ src = xpw; hi = xpw_hi; lo = xpw_lo; }
    else { j -= N4_XPW;               src = dtw; hi = dtw_hi; lo = dtw_lo; }

    float4 v = src[j];
    __half h0, l0, h1, l1, h2, l2, h3, l3;
    hsplit2(v.x, h0, l0); hsplit2(v.y, h1, l1);
    hsplit2(v.z, h2, l2); hsplit2(v.w, h3, l3);
    hi[j * 2 + 0] = __halves2half2(h0, h1);
    hi[j * 2 + 1] = __halves2half2(h2, h3);
    lo[j * 2 + 0] = __halves2half2(l0, l1);
    lo[j * 2 + 1] = __halves2half2(l2, l3);
}

// ---------------- split-K reduce for xdb + fused dt_in extract (fp16) ----------------
__global__ void xdb_reduce_kernel(const float* __restrict__ part,
                                  float* __restrict__ xdb,
                                  __half* __restrict__ dt16)
{
    int i = blockIdx.x * 256 + threadIdx.x;
    if (i >= ML * XDBW) return;
    float s = 0.f;
    #pragma unroll
    for (int z = 0; z < SPLITK; z++) s += part[(size_t)z * ML * XDBW + i];
    xdb[i] = s;
    int col = i % XDBW;
    if (col < DTR) {
        int row = i / XDBW;
        dt16[row * DTR + col] = __float2half(s);
    }
}

// ---------------- fused (optional add) + RMSNorm ----------------
__global__ void addnorm_kernel(const float* __restrict__ a,
                               const float* __restrict__ badd,
                               const float* __restrict__ w,
                               float* __restrict__ resid_out,
                               float* __restrict__ f32_out,
                               __half* __restrict__ h16_out)
{
    int row = blockIdx.x;
    const float* pa = a + (size_t)row * DD;
    const float* pb = badd ? badd + (size_t)row * DD : nullptr;

    float vals[4];
    float ss = 0.f;
    #pragma unroll
    for (int i = 0; i < 4; i++) {
        int d = threadIdx.x + i * 256;
        float v = pa[d];
        if (pb) v += pb[d];
        vals[i] = v;
        ss += v * v;
    }
    #pragma unroll
    for (int o = 16; o > 0; o >>= 1) ss += __shfl_xor_sync(0xffffffffu, ss, o);
    __shared__ float red[8];
    int wd = threadIdx.x >> 5;
    if ((threadIdx.x & 31) == 0) red[wd] = ss;
    __syncthreads();
    if (threadIdx.x < 32) {
        float v = (threadIdx.x < 8) ? red[threadIdx.x] : 0.f;
        #pragma unroll
        for (int o = 4; o > 0; o >>= 1) v += __shfl_xor_sync(0xffffffffu, v, o);
        if (threadIdx.x == 0) red[0] = v;
    }
    __syncthreads();
    float scale = rsqrtf(red[0] * (1.0f / DD) + 1e-5f);

    #pragma unroll
    for (int i = 0; i < 4; i++) {
        int d = threadIdx.x + i * 256;
        float hv = vals[i] * scale * w[d];
        size_t idx = (size_t)row * DD + d;
        if (resid_out) resid_out[idx] = vals[i];
        if (f32_out) f32_out[idx] = hv;
        if (h16_out) h16_out[idx] = __float2half(hv);
    }
}

// ---------------- causal depthwise conv (k=4) + SiLU; 4 timesteps per thread ----------------
__global__ void conv_silu_kernel(const float* __restrict__ xz,
                                 const float* __restrict__ cw,
                                 const float* __restrict__ cb,
                                 float* __restrict__ u,
                                 __half* __restrict__ u16)
{
    int idx = blockIdx.x * 256 + threadIdx.x;      // ML*EE/4 threads
    if (idx >= ML * EE / 4) return;
    int e = idx & (EE - 1);
    int g = idx >> 11;            // b*256 + l4
    int l0 = (g & 255) * 4;
    int b = g >> 8;

    const size_t rowstride = 2 * EE;
    const float* x = xz + ((size_t)(b * LL + l0)) * rowstride + e;

    float xm3 = 0.f, xm2 = 0.f, xm1 = 0.f;
    if (l0 > 0) {
        xm1 = x[-1 * (ptrdiff_t)rowstride];
        xm2 = x[-2 * (ptrdiff_t)rowstride];
        xm3 = x[-3 * (ptrdiff_t)rowstride];
    }
    float x0 = x[0];
    float x1 = x[1 * rowstride];
    float x2 = x[2 * rowstride];
    float x3 = x[3 * rowstride];

    float w0 = cw[e * 4 + 0], w1 = cw[e * 4 + 1], w2 = cw[e * 4 + 2], w3 = cw[e * 4 + 3];
    float bias = cb[e];

    float v[4];
    v[0] = bias + w0 * xm3 + w1 * xm2 + w2 * xm1 + w3 * x0;
    v[1] = bias + w0 * xm2 + w1 * xm1 + w2 * x0  + w3 * x1;
    v[2] = bias + w0 * xm1 + w1 * x0  + w2 * x1  + w3 * x2;
    v[3] = bias + w0 * x0  + w1 * x1  + w2 * x2  + w3 * x3;

    size_t oidx = ((size_t)(b * LL + l0)) * EE + e;
    #pragma unroll
    for (int j = 0; j < 4; j++) {
        float a = v[j];
        float uv = a / (1.f + __expf(-a));
        u[oidx + j * EE] = uv;
        u16[oidx + j * EE] = __float2half(uv);
    }
}

// ---------------- selective scan: smem-staged cooperative loads ----------------
// Block = 256 threads = 32 channels x 8 state-pair threads. cp.async stages
// dt/u/z (per channel) and B/C (per timestep) for 4 timesteps into a 4-deep ring.
__global__ void __launch_bounds__(256) scan_kernel(
    const float* __restrict__ dt,
    const float* __restrict__ ub,
    const float* __restrict__ xz,
    const float* __restrict__ xdb,
    const float* __restrict__ A_log,
    const float* __restrict__ Dp,
    __half* __restrict__ y16)
{
    // layout per [buf][step]: [0:32) dt, [32:64) u, [64:96) z, [96:112) B, [112:128) C
    __shared__ float sbuf[4][4][128];

    const int tid = threadIdx.x;
    const int c0 = blockIdx.x * 32;        // 32 channels per block (same batch)
    const int b  = c0 >> 11;
    const int ebase = c0 & (EE - 1);
    const int ch = tid >> 3;               // 0..31
    const int n2 = tid & 7;
    const int e = ebase + ch;
    const size_t bl0 = (size_t)b * LL;
    const uint32_t sB = smem_to_u32(sbuf);

    const float A0 = -__expf(A_log[e * NST + n2 * 2 + 0]);
    const float A1 = -__expf(A_log[e * NST + n2 * 2 + 1]);
    const float Dval = Dp[e];
    float h0 = 0.f, h1 = 0.f;

    auto load_group = [&](int g) {
        if (g < LL / 4 && tid < 128) {
            int j = tid >> 5;          // step 0..3
            int r = tid & 31;
            int seg = r >> 3;          // 0..3
            int q = r & 7;             // 16B chunk
            size_t bl = bl0 + (size_t)g * 4 + j;
            const float* src;
            if (seg == 0)      src = dt  + bl * EE + ebase + q * 4;
            else if (seg == 1) src = ub  + bl * EE + ebase + q * 4;
            else if (seg == 2) src = xz  + bl * 2 * EE + EE + ebase + q * 4;
            else               src = xdb + bl * XDBW + DTR + q * 4;   // B(16)+C(16)
            uint32_t dst = sB + (uint32_t)(((g & 3) * 4 + j) * 128 + seg * 32 + q * 4) * 4u;
            cp16(dst, src);
        }
        cp_commit();
    };

    load_group(0);
    load_group(1);
    load_group(2);

    for (int g = 0; g < LL / 4; g++) {
        cp_wait<2>();
        __syncthreads();
        load_group(g + 3);

        const float* buf0 = &sbuf[g & 3][0][0];
        #pragma unroll
        for (int j = 0; j < 4; j++) {
            const float* bp = buf0 + j * 128;
            float dtv = bp[ch], uv = bp[32 + ch], zv = bp[64 + ch];
            float Bx = bp[96 + 2 * n2], By = bp[97 + 2 * n2];
            float Cx = bp[112 + 2 * n2], Cy = bp[113 + 2 * n2];

            float dtu = dtv * uv;
            float dA0 = __expf(dtv * A0);
            float dA1 = __expf(dtv * A1);
            h0 = fmaf(dA0, h0, dtu * Bx);
            h1 = fmaf(dA1, h1, dtu * By);
            float p = fmaf(h0, Cx, h1 * Cy);
            p += __shfl_xor_sync(0xffffffffu, p, 1);
            p += __shfl_xor_sync(0xffffffffu, p, 2);
            p += __shfl_xor_sync(0xffffffffu, p, 4);
            if (n2 == 0) {
                float sig = 1.f / (1.f + __expf(-zv));
                float out = (p + uv * Dval) * (zv * sig);
                y16[(bl0 + (size_t)g * 4 + j) * EE + e] = __float2half(out);
            }
        }
    }
}

// ---------------- launch ----------------
extern "C" void kernel_launch(void* const* d_in, const int* in_sizes, int n_in,
                              void* d_out, int out_size)
{
    (void)in_sizes; (void)n_in; (void)out_size;
    const float* hidden = (const float*)d_in[0];
    const float* ipw    = (const float*)d_in[1];
    const float* cw     = (const float*)d_in[2];
    const float* cb     = (const float*)d_in[3];
    const float* xpw    = (const float*)d_in[4];
    const float* dtw    = (const float*)d_in[5];
    const float* dtb    = (const float*)d_in[6];
    const float* A_log  = (const float*)d_in[7];
    const float* Dp     = (const float*)d_in[8];
    const float* opw    = (const float*)d_in[9];
    const float* nw     = (const float*)d_in[10];
    const float* nfw    = (const float*)d_in[11];

    float *p_resid, *p_xz, *p_u, *p_xdb, *p_xdbp, *p_dt, *p_h;
    cudaGetSymbolAddress((void**)&p_resid, g_resid);
    cudaGetSymbolAddress((void**)&p_xz,    g_xz);
    cudaGetSymbolAddress((void**)&p_u,     g_u);
    cudaGetSymbolAddress((void**)&p_xdb,   g_xdb);
    cudaGetSymbolAddress((void**)&p_xdbp,  g_xdb_part);
    cudaGetSymbolAddress((void**)&p_dt,    g_dt);
    cudaGetSymbolAddress((void**)&p_h,     g_h);

    __half *ipw_hi, *ipw_lo, *xpw_hi, *xpw_lo, *dtw_hi, *dtw_lo, *opw_hi, *opw_lo;
    __half *hn16, *u16, *dt16, *y16;
    cudaGetSymbolAddress((void**)&ipw_hi, wb_ipw_hi); cudaGetSymbolAddress((void**)&ipw_lo, wb_ipw_lo);
    cudaGetSymbolAddress((void**)&xpw_hi, wb_xpw_hi); cudaGetSymbolAddress((void**)&xpw_lo, wb_xpw_lo);
    cudaGetSymbolAddress((void**)&dtw_hi, wb_dtw_hi); cudaGetSymbolAddress((void**)&dtw_lo, wb_dtw_lo);
    cudaGetSymbolAddress((void**)&opw_hi, wb_opw_hi); cudaGetSymbolAddress((void**)&opw_lo, wb_opw_lo);
    cudaGetSymbolAddress((void**)&hn16, a_hn16);
    cudaGetSymbolAddress((void**)&u16,  a_u16);
    cudaGetSymbolAddress((void**)&dt16, a_dt16);
    cudaGetSymbolAddress((void**)&y16,  a_y16);

    cudaFuncSetAttribute((const void*)hmma_gemm<0>, cudaFuncAttributeMaxDynamicSharedMemorySize, GSMEM);
    cudaFuncSetAttribute((const void*)hmma_gemm<1>, cudaFuncAttributeMaxDynamicSharedMemorySize, GSMEM);

    // one merged weight-split pass
    wsplit_all_kernel<<<(N4_ALL + 255) / 256, 256>>>(
        (const float4*)ipw, (const float4*)opw, (const float4*)xpw, (const float4*)dtw,
        (__half2*)ipw_hi, (__half2*)ipw_lo,
        (__half2*)opw_hi, (__half2*)opw_lo,
        (__half2*)xpw_hi, (__half2*)xpw_lo,
        (__half2*)dtw_hi, (__half2*)dtw_lo);

    for (int i = 0; i < NLAYER; i++) {
        const float* cw_i  = cw  + (size_t)i * EE * 4;
        const float* cb_i  = cb  + (size_t)i * EE;
        const float* dtb_i = dtb + (size_t)i * EE;
        const float* Al_i  = A_log + (size_t)i * EE * NST;
        const float* Dp_i  = Dp  + (size_t)i * EE;
        const float* nw_i  = nw  + (size_t)i * DD;

        if (i == 0)
            addnorm_kernel<<<ML, 256>>>(hidden, nullptr, nw_i, p_resid, nullptr, hn16);
        else
            addnorm_kernel<<<ML, 256>>>(p_resid, p_h, nw_i, p_resid, nullptr, hn16);

        // xz = hn @ ipw^T   (2048 x 4096 x 1024)
        hmma_gemm<0><<<dim3(32, 16, 1), 256, GSMEM>>>(
            hn16, ipw_hi + (size_t)i * 2 * EE * DD, ipw_lo + (size_t)i * 2 * EE * DD,
            p_xz, 4096, DD, DD, DD, 0, nullptr);

        // u = silu(conv(xi) + cb)
        conv_silu_kernel<<<(ML * EE / 4) / 256, 256>>>(p_xz, cw_i, cb_i, p_u, u16);

        // xdb partials = u @ xpw^T   (2048 x 96 x 2048), split-K x8
        hmma_gemm<0><<<dim3(1, 16, SPLITK), 256, GSMEM>>>(
            u16, xpw_hi + (size_t)i * XDBW * EE, xpw_lo + (size_t)i * XDBW * EE,
            p_xdbp, XDBW, EE / SPLITK, EE, EE, (size_t)ML * XDBW, nullptr);

        // reduce partials -> xdb; extract dt_in (fp16)
        xdb_reduce_kernel<<<(ML * XDBW + 255) / 256, 256>>>(p_xdbp, p_xdb, dt16);

        // dt = softplus(dt_in @ dtw^T + dtb)   (2048 x 2048 x 64)
        hmma_gemm<1><<<dim3(16, 16, 1), 256, GSMEM>>>(
            dt16, dtw_hi + (size_t)i * EE * DTR, dtw_lo + (size_t)i * EE * DTR,
            p_dt, EE, DTR, DTR, DTR, 0, dtb_i);

        // selective scan + skip + gate -> y (fp16)
        scan_kernel<<<(BB * EE) / 32, 256>>>(p_dt, p_u, p_xz, p_xdb, Al_i, Dp_i, y16);

        // h = y @ opw^T   (2048 x 1024 x 2048)
        hmma_gemm<0><<<dim3(8, 16, 1), 256, GSMEM>>>(
            y16, opw_hi + (size_t)i * DD * EE, opw_lo + (size_t)i * DD * EE,
            p_h, DD, EE, EE, EE, 0, nullptr);
    }

    addnorm_kernel<<<ML, 256>>>(p_h, p_resid, nfw, nullptr, (float*)d_out, nullptr);
}

// round 13
// speedup vs baseline: 1.2115x; 1.2115x over previous
#include <cuda_runtime.h>
#include <cuda_fp16.h>
#include <math.h>
#include <stdint.h>

#define BB 2
#define LL 1024
#define DD 1024
#define EE 2048
#define NST 16
#define DTR 64
#define NLAYER 4
#define ML (BB*LL)          // 2048
#define XDBW (DTR + 2*NST)  // 96
#define SPLITK 8

#define SZ_IPW (NLAYER*2*EE*DD)
#define SZ_XPW (NLAYER*XDBW*EE)
#define SZ_DTW (NLAYER*EE*DTR)
#define SZ_OPW (NLAYER*DD*EE)

// ---------------- scratch (device globals; no allocation) ----------------
__device__ __align__(16) float g_resid[ML*DD];
__device__ __align__(16) float g_xz[ML*2*EE];
__device__ __align__(16) float g_u[ML*EE];
__device__ __align__(16) float g_xdb[ML*XDBW];
__device__ __align__(16) float g_xdb_part[SPLITK*ML*XDBW];
__device__ __align__(16) float g_dt[ML*EE];
__device__ __align__(16) float g_h[ML*DD];

__device__ __align__(16) __half wb_ipw[SZ_IPW];
__device__ __align__(16) __half wb_xpw[SZ_XPW];
__device__ __align__(16) __half wb_dtw[SZ_DTW];
__device__ __align__(16) __half wb_opw[SZ_OPW];

__device__ __align__(16) __half a_hn16[ML*DD];
__device__ __align__(16) __half a_u16[ML*EE];
__device__ __align__(16) __half a_dt16[ML*DTR];
__device__ __align__(16) __half a_y16[ML*EE];

// ---------------- helpers ----------------
__device__ __forceinline__ uint32_t smem_to_u32(const void* p) {
    uint32_t a;
    asm("{ .reg .u64 t; cvta.to.shared.u64 t, %1; cvt.u32.u64 %0, t; }" : "=r"(a) : "l"(p));
    return a;
}
__device__ __forceinline__ void cp16(uint32_t s, const void* g) {
    asm volatile("cp.async.cg.shared.global [%0], [%1], 16;" :: "r"(s), "l"(g) : "memory");
}
__device__ __forceinline__ void cp16z(uint32_t s, const void* g, int srcsize) {
    asm volatile("cp.async.cg.shared.global [%0], [%1], 16, %2;"
                 :: "r"(s), "l"(g), "r"(srcsize) : "memory");
}
__device__ __forceinline__ void cp_commit() {
    asm volatile("cp.async.commit_group;" ::: "memory");
}
template <int N>
__device__ __forceinline__ void cp_wait() {
    asm volatile("cp.async.wait_group %0;" :: "n"(N) : "memory");
}
__device__ __forceinline__ void ldm_x4(uint32_t* r, uint32_t addr) {
    asm volatile("ldmatrix.sync.aligned.m8n8.x4.shared.b16 {%0,%1,%2,%3}, [%4];"
                 : "=r"(r[0]), "=r"(r[1]), "=r"(r[2]), "=r"(r[3]) : "r"(addr));
}
__device__ __forceinline__ void mma_f16(float* d, const uint32_t* a, uint32_t b0, uint32_t b1) {
    asm volatile(
        "mma.sync.aligned.m16n8k16.row.col.f32.f16.f16.f32 "
        "{%0,%1,%2,%3}, {%4,%5,%6,%7}, {%8,%9}, {%0,%1,%2,%3};"
        : "+f"(d[0]), "+f"(d[1]), "+f"(d[2]), "+f"(d[3])
        : "r"(a[0]), "r"(a[1]), "r"(a[2]), "r"(a[3]), "r"(b0), "r"(b1));
}

// ---------------- HMMA GEMM: C[M,N] = A16[M,K]*B16[N,K]^T (pure fp16, f32 accum) ----------------
// CTA tile 128x128, K-chunk 64 (4 x k16), 3-stage cp.async pipeline, 2 tiles/stage.
#define KC 64
#define NSTG 3
#define ROWB 144
#define TILE_B (128*ROWB)           // 18432
#define STAGE_B (2*TILE_B)          // 36864
#define GSMEM (NSTG*STAGE_B)        // 110592

template <int MODE>
__global__ void __launch_bounds__(256, 1)
hmma_gemm(const __half* __restrict__ A16, const __half* __restrict__ B16,
          float* __restrict__ C, int N, int Kloop, int lda, int ldb,
          size_t czstride, const float* __restrict__ bias)
{
    extern __shared__ char smem[];
    const uint32_t sb = smem_to_u32(smem);
    const int tid  = threadIdx.x;
    const int wid  = tid >> 5;
    const int lane = tid & 31;
    const int wm = wid >> 2;
    const int wn = wid & 3;
    const int row0 = blockIdx.y * 128;
    const int col0 = blockIdx.x * 128;
    const int kbase = blockIdx.z * Kloop;

    const int nc = Kloop / KC;

    auto stage_of = [&](int c) { int m = c % NSTG; return (uint32_t)m * STAGE_B; };

    auto load_chunk = [&](int c) {
        if (c < nc) {
            const uint32_t base = sb + stage_of(c);
            const int k0 = kbase + c * KC;
            #pragma unroll
            for (int it = 0; it < 8; it++) {
                int s = tid + it * 256;
                int tile = s >> 10;          // 0..1
                int r = (s >> 3) & 127;
                int seg = s & 7;
                uint32_t off = base + (uint32_t)tile * TILE_B + (uint32_t)(r * ROWB + seg * 16);
                if (tile == 0) {
                    const __half* g = A16 + ((size_t)(row0 + r) * lda + k0 + seg * 8);
                    cp16(off, g);
                } else {
                    const __half* g = B16 + ((size_t)(col0 + r) * ldb + k0 + seg * 8);
                    cp16z(off, g, (col0 + r < N) ? 16 : 0);
                }
            }
        }
        cp_commit();
    };

    float acc[4][4][4];
    #pragma unroll
    for (int i = 0; i < 4; i++)
        #pragma unroll
        for (int j = 0; j < 4; j++)
            #pragma unroll
            for (int k = 0; k < 4; k++) acc[i][j][k] = 0.f;

    load_chunk(0);
    load_chunk(1);

    for (int c = 0; c < nc; c++) {
        cp_wait<NSTG - 2>();
        __syncthreads();

        const uint32_t base = sb + stage_of(c);

        #pragma unroll
        for (int s = 0; s < 4; s++) {
            uint32_t af[4][4];      // [mtile][reg]
            uint32_t bf[2][4];      // [n16 block][reg]

            #pragma unroll
            for (int mi = 0; mi < 4; mi++) {
                uint32_t addr = base
                    + (uint32_t)((wm * 64 + mi * 16 + (lane & 15)) * ROWB
                                 + s * 32 + (lane >> 4) * 16);
                ldm_x4(af[mi], addr);
            }
            #pragma unroll
            for (int nb = 0; nb < 2; nb++) {
                uint32_t addr = base + (uint32_t)TILE_B
                    + (uint32_t)((wn * 32 + nb * 16 + ((lane >> 4) & 1) * 8 + (lane & 7)) * ROWB
                                 + ((lane >> 3) & 1) * 16 + s * 32);
                ldm_x4(bf[nb], addr);
            }

            if (s == 0) load_chunk(c + 2);

            #pragma unroll
            for (int mi = 0; mi < 4; mi++) {
                #pragma unroll
                for (int n = 0; n < 4; n++) {
                    int nb = n >> 1, o = (n & 1) * 2;
                    mma_f16(acc[mi][n], af[mi], bf[nb][o], bf[nb][o + 1]);
                }
            }
        }
    }

    float* Cz = C + (size_t)blockIdx.z * czstride;
    #pragma unroll
    for (int mi = 0; mi < 4; mi++) {
        #pragma unroll
        for (int n = 0; n < 4; n++) {
            int colb = col0 + wn * 32 + n * 8 + (lane & 3) * 2;
            #pragma unroll
            for (int half = 0; half < 2; half++) {
                int row = row0 + wm * 64 + mi * 16 + (lane >> 2) + half * 8;
                if (colb < N) {
                    float v0 = acc[mi][n][half * 2 + 0];
                    float v1 = acc[mi][n][half * 2 + 1];
                    if (MODE == 1) {
                        v0 += bias[colb];
                        v1 += bias[colb + 1];
                        v0 = (v0 > 20.f) ? v0 : log1pf(__expf(v0));
                        v1 = (v1 > 20.f) ? v1 : log1pf(__expf(v1));
                    }
                    *(float2*)&Cz[(size_t)row * N + colb] = make_float2(v0, v1);
                }
            }
        }
    }
}

// ---------------- merged weight convert (fp32 -> fp16), all 4 weights ----------------
#define N4_IPW (SZ_IPW/4)
#define N4_OPW (SZ_OPW/4)
#define N4_XPW (SZ_XPW/4)
#define N4_DTW (SZ_DTW/4)
#define N4_ALL (N4_IPW+N4_OPW+N4_XPW+N4_DTW)

__global__ void wconv_all_kernel(const float4* __restrict__ ipw,
                                 const float4* __restrict__ opw,
                                 const float4* __restrict__ xpw,
                                 const float4* __restrict__ dtw,
                                 __half2* __restrict__ ipw16,
                                 __half2* __restrict__ opw16,
                                 __half2* __restrict__ xpw16,
                                 __half2* __restrict__ dtw16)
{
    int i = blockIdx.x * 256 + threadIdx.x;
    if (i >= N4_ALL) return;
    const float4* src;
    __half2* dst;
    int j = i;
    if (j < N4_IPW)                 { src = ipw; dst = ipw16; }
    else if ((j -= N4_IPW) < N4_OPW){ src = opw; dst = opw16; }
    else if ((j -= N4_OPW) < N4_XPW){ src = xpw; dst = xpw16; }
    else { j -= N4_XPW;               src = dtw; dst = dtw16; }

    float4 v = src[j];
    dst[j * 2 + 0] = __floats2half2_rn(v.x, v.y);
    dst[j * 2 + 1] = __floats2half2_rn(v.z, v.w);
}

// ---------------- split-K reduce for xdb + fused dt_in extract (fp16) ----------------
__global__ void xdb_reduce_kernel(const float* __restrict__ part,
                                  float* __restrict__ xdb,
                                  __half* __restrict__ dt16)
{
    int i = blockIdx.x * 256 + threadIdx.x;
    if (i >= ML * XDBW) return;
    float s = 0.f;
    #pragma unroll
    for (int z = 0; z < SPLITK; z++) s += part[(size_t)z * ML * XDBW + i];
    xdb[i] = s;
    int col = i % XDBW;
    if (col < DTR) {
        int row = i / XDBW;
        dt16[row * DTR + col] = __float2half(s);
    }
}

// ---------------- fused (optional add) + RMSNorm ----------------
__global__ void addnorm_kernel(const float* __restrict__ a,
                               const float* __restrict__ badd,
                               const float* __restrict__ w,
                               float* __restrict__ resid_out,
                               float* __restrict__ f32_out,
                               __half* __restrict__ h16_out)
{
    int row = blockIdx.x;
    const float* pa = a + (size_t)row * DD;
    const float* pb = badd ? badd + (size_t)row * DD : nullptr;

    float vals[4];
    float ss = 0.f;
    #pragma unroll
    for (int i = 0; i < 4; i++) {
        int d = threadIdx.x + i * 256;
        float v = pa[d];
        if (pb) v += pb[d];
        vals[i] = v;
        ss += v * v;
    }
    #pragma unroll
    for (int o = 16; o > 0; o >>= 1) ss += __shfl_xor_sync(0xffffffffu, ss, o);
    __shared__ float red[8];
    int wd = threadIdx.x >> 5;
    if ((threadIdx.x & 31) == 0) red[wd] = ss;
    __syncthreads();
    if (threadIdx.x < 32) {
        float v = (threadIdx.x < 8) ? red[threadIdx.x] : 0.f;
        #pragma unroll
        for (int o = 4; o > 0; o >>= 1) v += __shfl_xor_sync(0xffffffffu, v, o);
        if (threadIdx.x == 0) red[0] = v;
    }
    __syncthreads();
    float scale = rsqrtf(red[0] * (1.0f / DD) + 1e-5f);

    #pragma unroll
    for (int i = 0; i < 4; i++) {
        int d = threadIdx.x + i * 256;
        float hv = vals[i] * scale * w[d];
        size_t idx = (size_t)row * DD + d;
        if (resid_out) resid_out[idx] = vals[i];
        if (f32_out) f32_out[idx] = hv;
        if (h16_out) h16_out[idx] = __float2half(hv);
    }
}

// ---------------- causal depthwise conv (k=4) + SiLU; 4 timesteps per thread ----------------
__global__ void conv_silu_kernel(const float* __restrict__ xz,
                                 const float* __restrict__ cw,
                                 const float* __restrict__ cb,
                                 float* __restrict__ u,
                                 __half* __restrict__ u16)
{
    int idx = blockIdx.x * 256 + threadIdx.x;      // ML*EE/4 threads
    if (idx >= ML * EE / 4) return;
    int e = idx & (EE - 1);
    int g = idx >> 11;            // b*256 + l4
    int l0 = (g & 255) * 4;
    int b = g >> 8;

    const size_t rowstride = 2 * EE;
    const float* x = xz + ((size_t)(b * LL + l0)) * rowstride + e;

    float xm3 = 0.f, xm2 = 0.f, xm1 = 0.f;
    if (l0 > 0) {
        xm1 = x[-1 * (ptrdiff_t)rowstride];
        xm2 = x[-2 * (ptrdiff_t)rowstride];
        xm3 = x[-3 * (ptrdiff_t)rowstride];
    }
    float x0 = x[0];
    float x1 = x[1 * rowstride];
    float x2 = x[2 * rowstride];
    float x3 = x[3 * rowstride];

    float w0 = cw[e * 4 + 0], w1 = cw[e * 4 + 1], w2 = cw[e * 4 + 2], w3 = cw[e * 4 + 3];
    float bias = cb[e];

    float v[4];
    v[0] = bias + w0 * xm3 + w1 * xm2 + w2 * xm1 + w3 * x0;
    v[1] = bias + w0 * xm2 + w1 * xm1 + w2 * x0  + w3 * x1;
    v[2] = bias + w0 * xm1 + w1 * x0  + w2 * x1  + w3 * x2;
    v[3] = bias + w0 * x0  + w1 * x1  + w2 * x2  + w3 * x3;

    size_t oidx = ((size_t)(b * LL + l0)) * EE + e;
    #pragma unroll
    for (int j = 0; j < 4; j++) {
        float a = v[j];
        float uv = a / (1.f + __expf(-a));
        u[oidx + j * EE] = uv;
        u16[oidx + j * EE] = __float2half(uv);
    }
}

// ---------------- selective scan: 8 threads/channel, 2 states/thread, prefetch 4 ----------------
__global__ void __launch_bounds__(256) scan_kernel(
    const float* __restrict__ dt,
    const float* __restrict__ ub,
    const float* __restrict__ xz,
    const float* __restrict__ xdb,
    const float* __restrict__ A_log,
    const float* __restrict__ Dp,
    __half* __restrict__ y16)
{
    int t = blockIdx.x * 256 + threadIdx.x;   // 0..32767
    int n2 = t & 7;                            // state pair 0..7
    int c = t >> 3;                            // channel 0..4095
    int b = c >> 11;
    int e = c & (EE - 1);

    const float A0 = -__expf(A_log[e * NST + n2 * 2 + 0]);
    const float A1 = -__expf(A_log[e * NST + n2 * 2 + 1]);
    const float Dval = Dp[e];
    float h0 = 0.f, h1 = 0.f;

    const float* pdt = dt + e;
    const float* pu  = ub + e;
    const float* pz  = xz + EE + e;
    const float2* pB = (const float2*)(xdb + DTR) + n2;
    const float2* pC = (const float2*)(xdb + DTR + NST) + n2;
    const size_t bl0 = (size_t)b * LL;
    const int XDBW2 = XDBW / 2;

    float fdt[4], fu[4], fz[4];
    float2 fB[4], fC[4];
    #pragma unroll
    for (int j = 0; j < 4; j++) {
        size_t bl = bl0 + j;
        fdt[j] = __ldg(pdt + bl * EE);
        fu[j]  = __ldg(pu + bl * EE);
        fz[j]  = __ldg(pz + bl * 2 * EE);
        fB[j]  = __ldg(pB + bl * XDBW2);
        fC[j]  = __ldg(pC + bl * XDBW2);
    }

    for (int l0 = 0; l0 < LL; l0 += 4) {
        float cdt[4], cu[4], cz[4];
        float2 cB[4], cC[4];
        #pragma unroll
        for (int j = 0; j < 4; j++) {
            cdt[j] = fdt[j]; cu[j] = fu[j]; cz[j] = fz[j]; cB[j] = fB[j]; cC[j] = fC[j];
        }
        if (l0 + 4 < LL) {
            #pragma unroll
            for (int j = 0; j < 4; j++) {
                size_t bl = bl0 + l0 + 4 + j;
                fdt[j] = __ldg(pdt + bl * EE);
                fu[j]  = __ldg(pu + bl * EE);
                fz[j]  = __ldg(pz + bl * 2 * EE);
                fB[j]  = __ldg(pB + bl * XDBW2);
                fC[j]  = __ldg(pC + bl * XDBW2);
            }
        }
        #pragma unroll
        for (int j = 0; j < 4; j++) {
            float dtv = cdt[j], uv = cu[j], zv = cz[j];
            float dtu = dtv * uv;
            float dA0 = __expf(dtv * A0);
            float dA1 = __expf(dtv * A1);
            h0 = fmaf(dA0, h0, dtu * cB[j].x);
            h1 = fmaf(dA1, h1, dtu * cB[j].y);
            float p = fmaf(h0, cC[j].x, h1 * cC[j].y);
            p += __shfl_xor_sync(0xffffffffu, p, 1);
            p += __shfl_xor_sync(0xffffffffu, p, 2);
            p += __shfl_xor_sync(0xffffffffu, p, 4);
            if (n2 == 0) {
                float sig = 1.f / (1.f + __expf(-zv));
                float out = (p + uv * Dval) * (zv * sig);
                y16[(bl0 + l0 + j) * EE + e] = __float2half(out);
            }
        }
    }
}

// ---------------- launch ----------------
extern "C" void kernel_launch(void* const* d_in, const int* in_sizes, int n_in,
                              void* d_out, int out_size)
{
    (void)in_sizes; (void)n_in; (void)out_size;
    const float* hidden = (const float*)d_in[0];
    const float* ipw    = (const float*)d_in[1];
    const float* cw     = (const float*)d_in[2];
    const float* cb     = (const float*)d_in[3];
    const float* xpw    = (const float*)d_in[4];
    const float* dtw    = (const float*)d_in[5];
    const float* dtb    = (const float*)d_in[6];
    const float* A_log  = (const float*)d_in[7];
    const float* Dp     = (const float*)d_in[8];
    const float* opw    = (const float*)d_in[9];
    const float* nw     = (const float*)d_in[10];
    const float* nfw    = (const float*)d_in[11];

    float *p_resid, *p_xz, *p_u, *p_xdb, *p_xdbp, *p_dt, *p_h;
    cudaGetSymbolAddress((void**)&p_resid, g_resid);
    cudaGetSymbolAddress((void**)&p_xz,    g_xz);
    cudaGetSymbolAddress((void**)&p_u,     g_u);
    cudaGetSymbolAddress((void**)&p_xdb,   g_xdb);
    cudaGetSymbolAddress((void**)&p_xdbp,  g_xdb_part);
    cudaGetSymbolAddress((void**)&p_dt,    g_dt);
    cudaGetSymbolAddress((void**)&p_h,     g_h);

    __half *ipw16, *xpw16, *dtw16, *opw16;
    __half *hn16, *u16, *dt16, *y16;
    cudaGetSymbolAddress((void**)&ipw16, wb_ipw);
    cudaGetSymbolAddress((void**)&xpw16, wb_xpw);
    cudaGetSymbolAddress((void**)&dtw16, wb_dtw);
    cudaGetSymbolAddress((void**)&opw16, wb_opw);
    cudaGetSymbolAddress((void**)&hn16, a_hn16);
    cudaGetSymbolAddress((void**)&u16,  a_u16);
    cudaGetSymbolAddress((void**)&dt16, a_dt16);
    cudaGetSymbolAddress((void**)&y16,  a_y16);

    cudaFuncSetAttribute((const void*)hmma_gemm<0>, cudaFuncAttributeMaxDynamicSharedMemorySize, GSMEM);
    cudaFuncSetAttribute((const void*)hmma_gemm<1>, cudaFuncAttributeMaxDynamicSharedMemorySize, GSMEM);

    // one merged weight-convert pass
    wconv_all_kernel<<<(N4_ALL + 255) / 256, 256>>>(
        (const float4*)ipw, (const float4*)opw, (const float4*)xpw, (const float4*)dtw,
        (__half2*)ipw16, (__half2*)opw16, (__half2*)xpw16, (__half2*)dtw16);

    for (int i = 0; i < NLAYER; i++) {
        const float* cw_i  = cw  + (size_t)i * EE * 4;
        const float* cb_i  = cb  + (size_t)i * EE;
        const float* dtb_i = dtb + (size_t)i * EE;
        const float* Al_i  = A_log + (size_t)i * EE * NST;
        const float* Dp_i  = Dp  + (size_t)i * EE;
        const float* nw_i  = nw  + (size_t)i * DD;

        if (i == 0)
            addnorm_kernel<<<ML, 256>>>(hidden, nullptr, nw_i, p_resid, nullptr, hn16);
        else
            addnorm_kernel<<<ML, 256>>>(p_resid, p_h, nw_i, p_resid, nullptr, hn16);

        // xz = hn @ ipw^T   (2048 x 4096 x 1024)
        hmma_gemm<0><<<dim3(32, 16, 1), 256, GSMEM>>>(
            hn16, ipw16 + (size_t)i * 2 * EE * DD,
            p_xz, 4096, DD, DD, DD, 0, nullptr);

        // u = silu(conv(xi) + cb)
        conv_silu_kernel<<<(ML * EE / 4) / 256, 256>>>(p_xz, cw_i, cb_i, p_u, u16);

        // xdb partials = u @ xpw^T   (2048 x 96 x 2048), split-K x8
        hmma_gemm<0><<<dim3(1, 16, SPLITK), 256, GSMEM>>>(
            u16, xpw16 + (size_t)i * XDBW * EE,
            p_xdbp, XDBW, EE / SPLITK, EE, EE, (size_t)ML * XDBW, nullptr);

        // reduce partials -> xdb; extract dt_in (fp16)
        xdb_reduce_kernel<<<(ML * XDBW + 255) / 256, 256>>>(p_xdbp, p_xdb, dt16);

        // dt = softplus(dt_in @ dtw^T + dtb)   (2048 x 2048 x 64)
        hmma_gemm<1><<<dim3(16, 16, 1), 256, GSMEM>>>(
            dt16, dtw16 + (size_t)i * EE * DTR,
            p_dt, EE, DTR, DTR, DTR, 0, dtb_i);

        // selective scan + skip + gate -> y (fp16)
        scan_kernel<<<(BB * EE * 8) / 256, 256>>>(p_dt, p_u, p_xz, p_xdb, Al_i, Dp_i, y16);

        // h = y @ opw^T   (2048 x 1024 x 2048)
        hmma_gemm<0><<<dim3(8, 16, 1), 256, GSMEM>>>(
            y16, opw16 + (size_t)i * DD * EE,
            p_h, DD, EE, EE, EE, 0, nullptr);
    }

    addnorm_kernel<<<ML, 256>>>(p_h, p_resid, nfw, nullptr, (float*)d_out, nullptr);
}

// round 14
// speedup vs baseline: 1.2536x; 1.0348x over previous
#include <cuda_runtime.h>
#include <cuda_fp16.h>
#include <math.h>
#include <stdint.h>

#define BB 2
#define LL 1024
#define DD 1024
#define EE 2048
#define NST 16
#define DTR 64
#define NLAYER 4
#define ML (BB*LL)          // 2048
#define XDBW (DTR + 2*NST)  // 96
#define SPLITK 8

#define SZ_IPW (NLAYER*2*EE*DD)
#define SZ_XPW (NLAYER*XDBW*EE)
#define SZ_DTW (NLAYER*EE*DTR)
#define SZ_OPW (NLAYER*DD*EE)

// ---------------- scratch (device globals; no allocation) ----------------
__device__ __align__(16) float g_resid[ML*DD];
__device__ __align__(16) float g_xz[ML*2*EE];
__device__ __align__(16) float g_u[ML*EE];
__device__ __align__(16) float g_xdb[ML*XDBW];
__device__ __align__(16) float g_xdb_part[SPLITK*ML*XDBW];
__device__ __align__(16) float g_dt[ML*EE];
__device__ __align__(16) float g_h[ML*DD];

__device__ __align__(16) __half wb_ipw[SZ_IPW];
__device__ __align__(16) __half wb_xpw[SZ_XPW];
__device__ __align__(16) __half wb_dtw[SZ_DTW];
__device__ __align__(16) __half wb_opw[SZ_OPW];

__device__ __align__(16) __half a_hn16[ML*DD];
__device__ __align__(16) __half a_u16[ML*EE];
__device__ __align__(16) __half a_dt16[ML*DTR];
__device__ __align__(16) __half a_y16[ML*EE];

// ---------------- helpers ----------------
__device__ __forceinline__ uint32_t smem_to_u32(const void* p) {
    uint32_t a;
    asm("{ .reg .u64 t; cvta.to.shared.u64 t, %1; cvt.u32.u64 %0, t; }" : "=r"(a) : "l"(p));
    return a;
}
__device__ __forceinline__ void cp16(uint32_t s, const void* g) {
    asm volatile("cp.async.cg.shared.global [%0], [%1], 16;" :: "r"(s), "l"(g) : "memory");
}
__device__ __forceinline__ void cp16z(uint32_t s, const void* g, int srcsize) {
    asm volatile("cp.async.cg.shared.global [%0], [%1], 16, %2;"
                 :: "r"(s), "l"(g), "r"(srcsize) : "memory");
}
__device__ __forceinline__ void cp_commit() {
    asm volatile("cp.async.commit_group;" ::: "memory");
}
template <int N>
__device__ __forceinline__ void cp_wait() {
    asm volatile("cp.async.wait_group %0;" :: "n"(N) : "memory");
}
__device__ __forceinline__ void ldm_x4(uint32_t* r, uint32_t addr) {
    asm volatile("ldmatrix.sync.aligned.m8n8.x4.shared.b16 {%0,%1,%2,%3}, [%4];"
                 : "=r"(r[0]), "=r"(r[1]), "=r"(r[2]), "=r"(r[3]) : "r"(addr));
}
__device__ __forceinline__ void mma_f16(float* d, const uint32_t* a, uint32_t b0, uint32_t b1) {
    asm volatile(
        "mma.sync.aligned.m16n8k16.row.col.f32.f16.f16.f32 "
        "{%0,%1,%2,%3}, {%4,%5,%6,%7}, {%8,%9}, {%0,%1,%2,%3};"
        : "+f"(d[0]), "+f"(d[1]), "+f"(d[2]), "+f"(d[3])
        : "r"(a[0]), "r"(a[1]), "r"(a[2]), "r"(a[3]), "r"(b0), "r"(b1));
}

// ---------------- HMMA GEMM: C[M,N] = A16[M,K]*B16[N,K]^T (pure fp16, f32 accum) ----------------
// CTA tile 128x128, K-chunk = KCH (64 or 128), 3-stage cp.async pipeline, 2 tiles/stage.
#define NSTG 3

template <int KCH> struct GP {
    static constexpr int ROWB   = (KCH == 128) ? 272 : 144;   // padded row bytes
    static constexpr int TILE_B = 128 * ROWB;
    static constexpr int STAGE_B = 2 * TILE_B;
    static constexpr int GSMEM  = NSTG * STAGE_B;
    static constexpr int SEGS   = KCH / 8;                    // 16B segs per row
    static constexpr int NSTEP  = KCH / 16;                   // k16 steps per chunk
    static constexpr int LOAD_ITERS = (2 * 128 * SEGS) / 256; // cp16 iters per chunk
};

template <int MODE, int KCH>
__global__ void __launch_bounds__(256, 1)
hmma_gemm(const __half* __restrict__ A16, const __half* __restrict__ B16,
          float* __restrict__ C, int N, int Kloop, int lda, int ldb,
          size_t czstride, const float* __restrict__ bias)
{
    using P = GP<KCH>;
    extern __shared__ char smem[];
    const uint32_t sb = smem_to_u32(smem);
    const int tid  = threadIdx.x;
    const int wid  = tid >> 5;
    const int lane = tid & 31;
    const int wm = wid >> 2;
    const int wn = wid & 3;
    const int row0 = blockIdx.y * 128;
    const int col0 = blockIdx.x * 128;
    const int kbase = blockIdx.z * Kloop;

    const int nc = Kloop / KCH;

    auto stage_of = [&](int c) { int m = c % NSTG; return (uint32_t)m * P::STAGE_B; };

    auto load_chunk = [&](int c) {
        if (c < nc) {
            const uint32_t base = sb + stage_of(c);
            const int k0 = kbase + c * KCH;
            #pragma unroll
            for (int it = 0; it < P::LOAD_ITERS; it++) {
                int s = tid + it * 256;
                int tile = s / (128 * P::SEGS);
                int rr = s % (128 * P::SEGS);
                int r = rr / P::SEGS;
                int seg = rr % P::SEGS;
                uint32_t off = base + (uint32_t)tile * P::TILE_B + (uint32_t)(r * P::ROWB + seg * 16);
                if (tile == 0) {
                    const __half* g = A16 + ((size_t)(row0 + r) * lda + k0 + seg * 8);
                    cp16(off, g);
                } else {
                    const __half* g = B16 + ((size_t)(col0 + r) * ldb + k0 + seg * 8);
                    cp16z(off, g, (col0 + r < N) ? 16 : 0);
                }
            }
        }
        cp_commit();
    };

    float acc[4][4][4];
    #pragma unroll
    for (int i = 0; i < 4; i++)
        #pragma unroll
        for (int j = 0; j < 4; j++)
            #pragma unroll
            for (int k = 0; k < 4; k++) acc[i][j][k] = 0.f;

    load_chunk(0);
    load_chunk(1);

    for (int c = 0; c < nc; c++) {
        cp_wait<NSTG - 2>();
        __syncthreads();

        const uint32_t base = sb + stage_of(c);

        #pragma unroll
        for (int s = 0; s < P::NSTEP; s++) {
            uint32_t af[4][4];      // [mtile][reg]
            uint32_t bf[2][4];      // [n16 block][reg]

            #pragma unroll
            for (int mi = 0; mi < 4; mi++) {
                uint32_t addr = base
                    + (uint32_t)((wm * 64 + mi * 16 + (lane & 15)) * P::ROWB
                                 + s * 32 + (lane >> 4) * 16);
                ldm_x4(af[mi], addr);
            }
            #pragma unroll
            for (int nb = 0; nb < 2; nb++) {
                uint32_t addr = base + (uint32_t)P::TILE_B
                    + (uint32_t)((wn * 32 + nb * 16 + ((lane >> 4) & 1) * 8 + (lane & 7)) * P::ROWB
                                 + ((lane >> 3) & 1) * 16 + s * 32);
                ldm_x4(bf[nb], addr);
            }

            if (s == 0) load_chunk(c + 2);

            #pragma unroll
            for (int mi = 0; mi < 4; mi++) {
                #pragma unroll
                for (int n = 0; n < 4; n++) {
                    int nb = n >> 1, o = (n & 1) * 2;
                    mma_f16(acc[mi][n], af[mi], bf[nb][o], bf[nb][o + 1]);
                }
            }
        }
    }

    float* Cz = C + (size_t)blockIdx.z * czstride;
    #pragma unroll
    for (int mi = 0; mi < 4; mi++) {
        #pragma unroll
        for (int n = 0; n < 4; n++) {
            int colb = col0 + wn * 32 + n * 8 + (lane & 3) * 2;
            #pragma unroll
            for (int half = 0; half < 2; half++) {
                int row = row0 + wm * 64 + mi * 16 + (lane >> 2) + half * 8;
                if (colb < N) {
                    float v0 = acc[mi][n][half * 2 + 0];
                    float v1 = acc[mi][n][half * 2 + 1];
                    if (MODE == 1) {
                        v0 += bias[colb];
                        v1 += bias[colb + 1];
                        v0 = (v0 > 20.f) ? v0 : log1pf(__expf(v0));
                        v1 = (v1 > 20.f) ? v1 : log1pf(__expf(v1));
                    }
                    *(float2*)&Cz[(size_t)row * N + colb] = make_float2(v0, v1);
                }
            }
        }
    }
}

#define GSMEM128 (GP<128>::GSMEM)   // 208896
#define GSMEM64  (GP<64>::GSMEM)    // 110592

// ---------------- merged weight convert (fp32 -> fp16), all 4 weights ----------------
#define N4_IPW (SZ_IPW/4)
#define N4_OPW (SZ_OPW/4)
#define N4_XPW (SZ_XPW/4)
#define N4_DTW (SZ_DTW/4)
#define N4_ALL (N4_IPW+N4_OPW+N4_XPW+N4_DTW)

__global__ void wconv_all_kernel(const float4* __restrict__ ipw,
                                 const float4* __restrict__ opw,
                                 const float4* __restrict__ xpw,
                                 const float4* __restrict__ dtw,
                                 __half2* __restrict__ ipw16,
                                 __half2* __restrict__ opw16,
                                 __half2* __restrict__ xpw16,
                                 __half2* __restrict__ dtw16)
{
    int i = blockIdx.x * 256 + threadIdx.x;
    if (i >= N4_ALL) return;
    const float4* src;
    __half2* dst;
    int j = i;
    if (j < N4_IPW)                 { src = ipw; dst = ipw16; }
    else if ((j -= N4_IPW) < N4_OPW){ src = opw; dst = opw16; }
    else if ((j -= N4_OPW) < N4_XPW){ src = xpw; dst = xpw16; }
    else { j -= N4_XPW;               src = dtw; dst = dtw16; }

    float4 v = src[j];
    dst[j * 2 + 0] = __floats2half2_rn(v.x, v.y);
    dst[j * 2 + 1] = __floats2half2_rn(v.z, v.w);
}

// ---------------- split-K reduce for xdb + fused dt_in extract (fp16) ----------------
__global__ void xdb_reduce_kernel(const float* __restrict__ part,
                                  float* __restrict__ xdb,
                                  __half* __restrict__ dt16)
{
    int i = blockIdx.x * 256 + threadIdx.x;
    if (i >= ML * XDBW) return;
    float s = 0.f;
    #pragma unroll
    for (int z = 0; z < SPLITK; z++) s += part[(size_t)z * ML * XDBW + i];
    xdb[i] = s;
    int col = i % XDBW;
    if (col < DTR) {
        int row = i / XDBW;
        dt16[row * DTR + col] = __float2half(s);
    }
}

// ---------------- fused (optional add) + RMSNorm ----------------
__global__ void addnorm_kernel(const float* __restrict__ a,
                               const float* __restrict__ badd,
                               const float* __restrict__ w,
                               float* __restrict__ resid_out,
                               float* __restrict__ f32_out,
                               __half* __restrict__ h16_out)
{
    int row = blockIdx.x;
    const float* pa = a + (size_t)row * DD;
    const float* pb = badd ? badd + (size_t)row * DD : nullptr;

    float vals[4];
    float ss = 0.f;
    #pragma unroll
    for (int i = 0; i < 4; i++) {
        int d = threadIdx.x + i * 256;
        float v = pa[d];
        if (pb) v += pb[d];
        vals[i] = v;
        ss += v * v;
    }
    #pragma unroll
    for (int o = 16; o > 0; o >>= 1) ss += __shfl_xor_sync(0xffffffffu, ss, o);
    __shared__ float red[8];
    int wd = threadIdx.x >> 5;
    if ((threadIdx.x & 31) == 0) red[wd] = ss;
    __syncthreads();
    if (threadIdx.x < 32) {
        float v = (threadIdx.x < 8) ? red[threadIdx.x] : 0.f;
        #pragma unroll
        for (int o = 4; o > 0; o >>= 1) v += __shfl_xor_sync(0xffffffffu, v, o);
        if (threadIdx.x == 0) red[0] = v;
    }
    __syncthreads();
    float scale = rsqrtf(red[0] * (1.0f / DD) + 1e-5f);

    #pragma unroll
    for (int i = 0; i < 4; i++) {
        int d = threadIdx.x + i * 256;
        float hv = vals[i] * scale * w[d];
        size_t idx = (size_t)row * DD + d;
        if (resid_out) resid_out[idx] = vals[i];
        if (f32_out) f32_out[idx] = hv;
        if (h16_out) h16_out[idx] = __float2half(hv);
    }
}

// ---------------- causal depthwise conv (k=4) + SiLU; 4 timesteps per thread ----------------
__global__ void conv_silu_kernel(const float* __restrict__ xz,
                                 const float* __restrict__ cw,
                                 const float* __restrict__ cb,
                                 float* __restrict__ u,
                                 __half* __restrict__ u16)
{
    int idx = blockIdx.x * 256 + threadIdx.x;      // ML*EE/4 threads
    if (idx >= ML * EE / 4) return;
    int e = idx & (EE - 1);
    int g = idx >> 11;            // b*256 + l4
    int l0 = (g & 255) * 4;
    int b = g >> 8;

    const size_t rowstride = 2 * EE;
    const float* x = xz + ((size_t)(b * LL + l0)) * rowstride + e;

    float xm3 = 0.f, xm2 = 0.f, xm1 = 0.f;
    if (l0 > 0) {
        xm1 = x[-1 * (ptrdiff_t)rowstride];
        xm2 = x[-2 * (ptrdiff_t)rowstride];
        xm3 = x[-3 * (ptrdiff_t)rowstride];
    }
    float x0 = x[0];
    float x1 = x[1 * rowstride];
    float x2 = x[2 * rowstride];
    float x3 = x[3 * rowstride];

    float w0 = cw[e * 4 + 0], w1 = cw[e * 4 + 1], w2 = cw[e * 4 + 2], w3 = cw[e * 4 + 3];
    float bias = cb[e];

    float v[4];
    v[0] = bias + w0 * xm3 + w1 * xm2 + w2 * xm1 + w3 * x0;
    v[1] = bias + w0 * xm2 + w1 * xm1 + w2 * x0  + w3 * x1;
    v[2] = bias + w0 * xm1 + w1 * x0  + w2 * x1  + w3 * x2;
    v[3] = bias + w0 * x0  + w1 * x1  + w2 * x2  + w3 * x3;

    size_t oidx = ((size_t)(b * LL + l0)) * EE + e;
    #pragma unroll
    for (int j = 0; j < 4; j++) {
        float a = v[j];
        float uv = a / (1.f + __expf(-a));
        u[oidx + j * EE] = uv;
        u16[oidx + j * EE] = __float2half(uv);
    }
}

// ---------------- selective scan: 8 threads/channel, 2 states/thread, prefetch 4 ----------------
__global__ void __launch_bounds__(256) scan_kernel(
    const float* __restrict__ dt,
    const float* __restrict__ ub,
    const float* __restrict__ xz,
    const float* __restrict__ xdb,
    const float* __restrict__ A_log,
    const float* __restrict__ Dp,
    __half* __restrict__ y16)
{
    int t = blockIdx.x * 256 + threadIdx.x;   // 0..32767
    int n2 = t & 7;                            // state pair 0..7
    int c = t >> 3;                            // channel 0..4095
    int b = c >> 11;
    int e = c & (EE - 1);

    const float A0 = -__expf(A_log[e * NST + n2 * 2 + 0]);
    const float A1 = -__expf(A_log[e * NST + n2 * 2 + 1]);
    const float Dval = Dp[e];
    float h0 = 0.f, h1 = 0.f;

    const float* pdt = dt + e;
    const float* pu  = ub + e;
    const float* pz  = xz + EE + e;
    const float2* pB = (const float2*)(xdb + DTR) + n2;
    const float2* pC = (const float2*)(xdb + DTR + NST) + n2;
    const size_t bl0 = (size_t)b * LL;
    const int XDBW2 = XDBW / 2;

    float fdt[4], fu[4], fz[4];
    float2 fB[4], fC[4];
    #pragma unroll
    for (int j = 0; j < 4; j++) {
        size_t bl = bl0 + j;
        fdt[j] = __ldg(pdt + bl * EE);
        fu[j]  = __ldg(pu + bl * EE);
        fz[j]  = __ldg(pz + bl * 2 * EE);
        fB[j]  = __ldg(pB + bl * XDBW2);
        fC[j]  = __ldg(pC + bl * XDBW2);
    }

    for (int l0 = 0; l0 < LL; l0 += 4) {
        float cdt[4], cu[4], cz[4];
        float2 cB[4], cC[4];
        #pragma unroll
        for (int j = 0; j < 4; j++) {
            cdt[j] = fdt[j]; cu[j] = fu[j]; cz[j] = fz[j]; cB[j] = fB[j]; cC[j] = fC[j];
        }
        if (l0 + 4 < LL) {
            #pragma unroll
            for (int j = 0; j < 4; j++) {
                size_t bl = bl0 + l0 + 4 + j;
                fdt[j] = __ldg(pdt + bl * EE);
                fu[j]  = __ldg(pu + bl * EE);
                fz[j]  = __ldg(pz + bl * 2 * EE);
                fB[j]  = __ldg(pB + bl * XDBW2);
                fC[j]  = __ldg(pC + bl * XDBW2);
            }
        }
        #pragma unroll
        for (int j = 0; j < 4; j++) {
            float dtv = cdt[j], uv = cu[j], zv = cz[j];
            float dtu = dtv * uv;
            float dA0 = __expf(dtv * A0);
            float dA1 = __expf(dtv * A1);
            h0 = fmaf(dA0, h0, dtu * cB[j].x);
            h1 = fmaf(dA1, h1, dtu * cB[j].y);
            float p = fmaf(h0, cC[j].x, h1 * cC[j].y);
            p += __shfl_xor_sync(0xffffffffu, p, 1);
            p += __shfl_xor_sync(0xffffffffu, p, 2);
            p += __shfl_xor_sync(0xffffffffu, p, 4);
            if (n2 == 0) {
                float sig = 1.f / (1.f + __expf(-zv));
                float out = (p + uv * Dval) * (zv * sig);
                y16[(bl0 + l0 + j) * EE + e] = __float2half(out);
            }
        }
    }
}

// ---------------- launch ----------------
extern "C" void kernel_launch(void* const* d_in, const int* in_sizes, int n_in,
                              void* d_out, int out_size)
{
    (void)in_sizes; (void)n_in; (void)out_size;
    const float* hidden = (const float*)d_in[0];
    const float* ipw    = (const float*)d_in[1];
    const float* cw     = (const float*)d_in[2];
    const float* cb     = (const float*)d_in[3];
    const float* xpw    = (const float*)d_in[4];
    const float* dtw    = (const float*)d_in[5];
    const float* dtb    = (const float*)d_in[6];
    const float* A_log  = (const float*)d_in[7];
    const float* Dp     = (const float*)d_in[8];
    const float* opw    = (const float*)d_in[9];
    const float* nw     = (const float*)d_in[10];
    const float* nfw    = (const float*)d_in[11];

    float *p_resid, *p_xz, *p_u, *p_xdb, *p_xdbp, *p_dt, *p_h;
    cudaGetSymbolAddress((void**)&p_resid, g_resid);
    cudaGetSymbolAddress((void**)&p_xz,    g_xz);
    cudaGetSymbolAddress((void**)&p_u,     g_u);
    cudaGetSymbolAddress((void**)&p_xdb,   g_xdb);
    cudaGetSymbolAddress((void**)&p_xdbp,  g_xdb_part);
    cudaGetSymbolAddress((void**)&p_dt,    g_dt);
    cudaGetSymbolAddress((void**)&p_h,     g_h);

    __half *ipw16, *xpw16, *dtw16, *opw16;
    __half *hn16, *u16, *dt16, *y16;
    cudaGetSymbolAddress((void**)&ipw16, wb_ipw);
    cudaGetSymbolAddress((void**)&xpw16, wb_xpw);
    cudaGetSymbolAddress((void**)&dtw16, wb_dtw);
    cudaGetSymbolAddress((void**)&opw16, wb_opw);
    cudaGetSymbolAddress((void**)&hn16, a_hn16);
    cudaGetSymbolAddress((void**)&u16,  a_u16);
    cudaGetSymbolAddress((void**)&dt16, a_dt16);
    cudaGetSymbolAddress((void**)&y16,  a_y16);

    cudaFuncSetAttribute((const void*)hmma_gemm<0,128>, cudaFuncAttributeMaxDynamicSharedMemorySize, GSMEM128);
    cudaFuncSetAttribute((const void*)hmma_gemm<1,64>,  cudaFuncAttributeMaxDynamicSharedMemorySize, GSMEM64);

    // one merged weight-convert pass
    wconv_all_kernel<<<(N4_ALL + 255) / 256, 256>>>(
        (const float4*)ipw, (const float4*)opw, (const float4*)xpw, (const float4*)dtw,
        (__half2*)ipw16, (__half2*)opw16, (__half2*)xpw16, (__half2*)dtw16);

    for (int i = 0; i < NLAYER; i++) {
        const float* cw_i  = cw  + (size_t)i * EE * 4;
        const float* cb_i  = cb  + (size_t)i * EE;
        const float* dtb_i = dtb + (size_t)i * EE;
        const float* Al_i  = A_log + (size_t)i * EE * NST;
        const float* Dp_i  = Dp  + (size_t)i * EE;
        const float* nw_i  = nw  + (size_t)i * DD;

        if (i == 0)
            addnorm_kernel<<<ML, 256>>>(hidden, nullptr, nw_i, p_resid, nullptr, hn16);
        else
            addnorm_kernel<<<ML, 256>>>(p_resid, p_h, nw_i, p_resid, nullptr, hn16);

        // xz = hn @ ipw^T   (2048 x 4096 x 1024)
        hmma_gemm<0,128><<<dim3(32, 16, 1), 256, GSMEM128>>>(
            hn16, ipw16 + (size_t)i * 2 * EE * DD,
            p_xz, 4096, DD, DD, DD, 0, nullptr);

        // u = silu(conv(xi) + cb)
        conv_silu_kernel<<<(ML * EE / 4) / 256, 256>>>(p_xz, cw_i, cb_i, p_u, u16);

        // xdb partials = u @ xpw^T   (2048 x 96 x 2048), split-K x8 (Kloop=256 -> 2 chunks)
        hmma_gemm<0,128><<<dim3(1, 16, SPLITK), 256, GSMEM128>>>(
            u16, xpw16 + (size_t)i * XDBW * EE,
            p_xdbp, XDBW, EE / SPLITK, EE, EE, (size_t)ML * XDBW, nullptr);

        // reduce partials -> xdb; extract dt_in (fp16)
        xdb_reduce_kernel<<<(ML * XDBW + 255) / 256, 256>>>(p_xdbp, p_xdb, dt16);

        // dt = softplus(dt_in @ dtw^T + dtb)   (2048 x 2048 x 64) — K=64 chunk
        hmma_gemm<1,64><<<dim3(16, 16, 1), 256, GSMEM64>>>(
            dt16, dtw16 + (size_t)i * EE * DTR,
            p_dt, EE, DTR, DTR, DTR, 0, dtb_i);

        // selective scan + skip + gate -> y (fp16)
        scan_kernel<<<(BB * EE * 8) / 256, 256>>>(p_dt, p_u, p_xz, p_xdb, Al_i, Dp_i, y16);

        // h = y @ opw^T   (2048 x 1024 x 2048)
        hmma_gemm<0,128><<<dim3(8, 16, 1), 256, GSMEM128>>>(
            y16, opw16 + (size_t)i * DD * EE,
            p_h, DD, EE, EE, EE, 0, nullptr);
    }

    addnorm_kernel<<<ML, 256>>>(p_h, p_resid, nfw, nullptr, (float*)d_out, nullptr);
}